// round 8
// baseline (speedup 1.0000x reference)
#include <cuda_runtime.h>
#include <cstdint>

// ---------------------------------------------------------------------------
// out[b,c] = sum_e y[b,e]*( sum_{w<=v<=i} S3[c,e,(w,v,i)] x_w x_v x_i
//                         + sum_{w<=v}    S2[c,e,(w,v)]   x_w x_v
//                         + sum_w         V1[c,e,w]       x_w )
// Round 7: 2 b's/thread @ 1024 threads (occ 25->50%), LDS.128 S3 streams
// (even-padded pair lengths), scalar y.
// ---------------------------------------------------------------------------

namespace {
constexpr int LDIM = 16;
constexpr int EDIM = 10;
constexpr int CDIM = 256;
constexpr int BDIM = 1024;
constexpr int K3C  = 23;
constexpr int K2C  = 4;

constexpr int NPAIR    = 136;           // (w<=v) pairs, 8 buckets x 17
constexpr int NBUCK    = 8;
constexpr int PPB      = 17;
constexpr int BSTRIDE  = 72;            // ull slots per bucket (even-padded, max 68)
constexpr int NSLOT_U  = NBUCK * BSTRIDE;   // 576 ull per e
constexpr int NSLOT_U2 = NSLOT_U / 2;       // 288 ull2 per e
constexpr int NSLOT_F  = 2 * NSLOT_U;       // 1152 floats per e

constexpr int S3_PER_C  = EDIM * NSLOT_F;   // 11520 floats
constexpr int S2U_PER_C = EDIM * NPAIR;     // 1360 ull
constexpr int V1_PER_C  = EDIM * LDIM;      // 160

constexpr int SMEM_MAIN =
    S3_PER_C * 4 +        // 46080
    S2U_PER_C * 8 +       // 10880
    256 * 17 * 4 +        // 17408 x scalars, stride 17
    EDIM * 256 * 4 +      // 10240 scalar y [e][b]
    NPAIR * 4 * 4 +       //  2176 tables (w,v,off,M)
    8 * 256 * 4;          //  8192 reduction
// = 94976

constexpr int SMEM_KS3 = (K3C * NSLOT_F + EDIM * K3C + 8) * 4;  // ~107 KB
}

// ---- device scratch ----------------------------------------------------------
__device__ int   g_pw[NPAIR], g_pv[NPAIR], g_off[NPAIR], g_m[NPAIR];
__device__ int   g_s2p[NSLOT_F], g_s2i[NSLOT_F];   // float-slot -> pair, i
__device__ float U3symT[K3C * NSLOT_F];            // [k][slot], zero-padded
__device__ float S3g[CDIM * S3_PER_C];             // ~11.8 MB
__device__ unsigned long long S2gu[CDIM * S2U_PER_C];
__device__ float V1g[CDIM * V1_PER_C];

// ---- packed f32x2 helpers (sm_103a) -------------------------------------------
using ull = unsigned long long;
__device__ __forceinline__ ull pk2(float a, float b) {
    ull r;
    asm("mov.b64 %0, {%1, %2};"
        : "=l"(r) : "r"(__float_as_uint(a)), "r"(__float_as_uint(b)));
    return r;
}
__device__ __forceinline__ ull dup2(float a) {
    ull r;
    asm("mov.b64 %0, {%1, %1};" : "=l"(r) : "r"(__float_as_uint(a)));
    return r;
}
__device__ __forceinline__ ull fma2(ull a, ull b, ull c) {
    ull d;
    asm("fma.rn.f32x2 %0, %1, %2, %3;" : "=l"(d) : "l"(a), "l"(b), "l"(c));
    return d;
}
__device__ __forceinline__ void upk2(ull v, float& a, float& b) {
    unsigned int lo, hi;
    asm("mov.b64 {%0, %1}, %2;" : "=r"(lo), "=r"(hi) : "l"(v));
    a = __uint_as_float(lo);
    b = __uint_as_float(hi);
}

// ---- k_tab: parallel table builder, balanced buckets, EVEN-padded lengths -----
__device__ __forceinline__ int len_of_rank(int r) {
    int o = 0, L = 8;
    while (L > 1 && o + 4 * (8 - L) + 3 <= r) { o += 4 * (8 - L) + 3; L--; }
    return L;
}
__global__ void k_tab() {
    const int tid = threadIdx.x;
    for (int s = tid; s < NSLOT_F; s += 256) { g_s2i[s] = -1; g_s2p[s] = 0; }
    __syncthreads();
    if (tid >= NPAIR) return;

    int p = tid, w = 0;
    while (p >= LDIM - w) { p -= LDIM - w; w++; }
    const int v = w + p;
    const int g = v >> 1;
    const int L = 8 - g;

    int idx = 0;
    for (int w2 = 0; w2 < w; w2++) {
        if (2 * g     >= w2) idx++;
        if (2 * g + 1 >= w2) idx++;
    }
    if ((v & 1) && (2 * g >= w)) idx++;
    int offL = 0;
    for (int L2 = 8; L2 > L; L2--) offL += 4 * (8 - L2) + 3;
    const int rank   = offL + idx;
    const int bucket = rank & 7;
    const int j      = rank >> 3;

    // offsets use ceil-to-even lengths (16B alignment for LDS.128)
    int off_local = 0;
    for (int j2 = 0; j2 < j; j2++) {
        const int L2 = len_of_rank(j2 * 8 + bucket);
        off_local += (L2 + 1) & ~1;
    }

    const int off_abs = bucket * BSTRIDE + off_local;   // even
    const int pi = bucket * PPB + j;
    g_pw[pi]  = w;
    g_pv[pi]  = v;
    g_off[pi] = off_abs;
    g_m[pi]   = (L + 1) >> 1;   // ull2 count

    for (int u = 0; u < L; u++)
        for (int r = 0; r < 2; r++) {
            const int s = 2 * (off_abs + u) + r;
            const int i = 14 - 2 * u + r;
            g_s2p[s] = pi;
            g_s2i[s] = (i >= v) ? i : -1;
        }
    // padding slots (u in [L, 2*M)) stay -1 -> zeros in U3symT/S3g
}

// ---- k_sym: symmetrized U3, transposed [k][slot] ------------------------------
__device__ __forceinline__ float u3at(const float* U3, int a, int b, int c, int k) {
    return U3[((a * 16 + b) * 16 + c) * K3C + k];
}
__global__ void k_sym(const float* __restrict__ U3) {
    const int idx = blockIdx.x * 256 + threadIdx.x;   // 23 * 1152
    if (idx >= K3C * NSLOT_F) return;
    const int s = idx % NSLOT_F;
    const int k = idx / NSLOT_F;
    const int i = g_s2i[s];
    float val = 0.f;
    if (i >= 0) {
        const int pi = g_s2p[s];
        const int w = g_pw[pi], v = g_pv[pi];
        if (w == v && v == i) {
            val = u3at(U3, w, w, w, k);
        } else if (w == v) {
            val = u3at(U3, w, w, i, k) + u3at(U3, w, i, w, k) + u3at(U3, i, w, w, k);
        } else if (v == i) {
            val = u3at(U3, w, v, v, k) + u3at(U3, v, w, v, k) + u3at(U3, v, v, w, k);
        } else {
            val = u3at(U3, w, v, i, k) + u3at(U3, w, i, v, k) +
                  u3at(U3, v, w, i, k) + u3at(U3, v, i, w, k) +
                  u3at(U3, i, w, v, k) + u3at(U3, i, v, w, k);
        }
    }
    U3symT[k * NSLOT_F + s] = val;
}

// ---- k_s3: per-c contraction + fused S2/V1 ------------------------------------
__global__ __launch_bounds__(512, 1)
void k_s3(const float* __restrict__ W3, const float* __restrict__ U2,
          const float* __restrict__ W2, const float* __restrict__ U1,
          const float* __restrict__ W1) {
    extern __shared__ float sm[];
    float* sU = sm;                       // [23][1152]
    float* sW = sm + K3C * NSLOT_F;       // [10][23]
    const int tid = threadIdx.x;
    const int c   = blockIdx.x;

    for (int t = tid; t < K3C * NSLOT_F; t += 512) sU[t] = U3symT[t];
    if (tid < EDIM * K3C) {
        const int e = tid / K3C, k = tid - e * K3C;
        sW[tid] = W3[(e * K3C + k) * CDIM + c];
    }
    __syncthreads();

#pragma unroll 1
    for (int idx = tid; idx < S3_PER_C; idx += 512) {
        const int e = idx / NSLOT_F;
        const int s = idx - e * NSLOT_F;
        float a = 0.f;
#pragma unroll
        for (int k = 0; k < K3C; k++)
            a = fmaf(sU[k * NSLOT_F + s], sW[e * K3C + k], a);
        S3g[c * S3_PER_C + idx] = a;
    }

    for (int t = tid; t < S2U_PER_C; t += 512) {
        const int e = t / NPAIR, pp = t - e * NPAIR;
        const int w = g_pw[pp], v = g_pv[pp];
        float s = 0.f;
#pragma unroll
        for (int k = 0; k < K2C; k++) {
            float u = U2[(w * 16 + v) * K2C + k];
            if (w != v) u += U2[(v * 16 + w) * K2C + k];
            s = fmaf(u, W2[(e * K2C + k) * CDIM + c], s);
        }
        S2gu[c * S2U_PER_C + t] = (ull)__float_as_uint(s);  // (s, 0)
    }
    if (tid < V1_PER_C) {
        const int e = tid >> 4, w = tid & 15;
        V1g[c * V1_PER_C + tid] = U1[w] * W1[e * CDIM + c];
    }
}

// ---- sc_main: single-pair dot, ulonglong2 stream loads, 2 b's/thread -----------
template <int M>
__device__ __forceinline__ void dot_block(
    const ulonglong2* __restrict__ sS3u2, int off2, const ull* __restrict__ s2p,
    const float* __restrict__ sYs, int bg,
    const ull (&xp0)[8], const ull (&xp1)[8],
    ull& ya0, ull& ya1)
{
#pragma unroll 1
    for (int e = 0; e < EDIM; e++) {
        const ulonglong2* st = sS3u2 + e * NSLOT_U2 + off2;
        const ull s2 = s2p[e * NPAIR];
        ull d0 = s2, d1 = s2;
#pragma unroll
        for (int m = 0; m < M; m++) {
            const ulonglong2 t = st[m];            // LDS.128 broadcast
            d0 = fma2(t.x, xp0[7 - 2 * m], d0);
            d1 = fma2(t.x, xp1[7 - 2 * m], d1);
            d0 = fma2(t.y, xp0[6 - 2 * m], d0);
            d1 = fma2(t.y, xp1[6 - 2 * m], d1);
        }
        const float* yrow = sYs + e * 256;
        ya0 = fma2(d0, dup2(yrow[bg]), ya0);
        ya1 = fma2(d1, dup2(yrow[bg + 128]), ya1);
    }
}

// Grid (c=256, btile=4). 1024 threads: bg = tid&127 owns b's {bg, bg+128};
// psplit = tid>>7 owns one balanced bucket of 17 pairs.
__global__ __launch_bounds__(1024, 1)
void sc_main(const float* __restrict__ x, const float* __restrict__ y,
             float* __restrict__ out) {
    extern __shared__ char smraw[];
    float* sS3 = reinterpret_cast<float*>(smraw);
    ull*   sS2 = reinterpret_cast<ull*>(sS3 + S3_PER_C);
    float* sXs = reinterpret_cast<float*>(sS2 + S2U_PER_C);
    float* sYs = sXs + 256 * 17;
    int*   sPW = reinterpret_cast<int*>(sYs + EDIM * 256);
    int*   sPV = sPW + NPAIR;
    int*   sOF = sPV + NPAIR;
    int*   sM  = sOF + NPAIR;
    float* red = reinterpret_cast<float*>(sM + NPAIR);
    const ulonglong2* sS3u2 = reinterpret_cast<const ulonglong2*>(sS3);

    const int tid    = threadIdx.x;
    const int c      = blockIdx.x;
    const int base   = blockIdx.y * 256;
    const int bg     = tid & 127;
    const int psplit = tid >> 7;

    // ---- stage S3 / S2 (coalesced) ----
    {
        const float4* src = reinterpret_cast<const float4*>(S3g + c * S3_PER_C);
        float4* dst = reinterpret_cast<float4*>(sS3);
        for (int t = tid; t < S3_PER_C / 4; t += 1024) dst[t] = src[t];
        for (int t = tid; t < S2U_PER_C; t += 1024)
            sS2[t] = S2gu[c * S2U_PER_C + t];
    }
    // ---- stage x scalars ----
#pragma unroll
    for (int t = 0; t < 4; t++) {
        const int idx = tid + t * 1024;           // 4096 = 256*16
        const int b = idx >> 4, i = idx & 15;
        sXs[b * 17 + i] = x[((base + b) * CDIM + c) * LDIM + i];
    }
    // ---- stage scalar y [e][b] ----
    for (int idx = tid; idx < EDIM * 256; idx += 1024) {
        const int b = idx & 255, e = idx >> 8;
        sYs[e * 256 + b] = y[(base + b) * EDIM + e];
    }
    if (tid < NPAIR) {
        sPW[tid] = g_pw[tid];
        sPV[tid] = g_pv[tid];
        sOF[tid] = g_off[tid];
        sM[tid]  = g_m[tid];
    }
    __syncthreads();

    // ---- per-thread packed x (2 b's) ----
    const int b0 = bg, b1 = bg + 128;
    ull xp0[8], xp1[8];
#pragma unroll
    for (int q = 0; q < 8; q++) {
        xp0[q] = pk2(sXs[b0 * 17 + 2 * q], sXs[b0 * 17 + 2 * q + 1]);
        xp1[q] = pk2(sXs[b1 * 17 + 2 * q], sXs[b1 * 17 + 2 * q + 1]);
    }

    ull acc0 = 0ull, acc1 = 0ull;

#pragma unroll 1
    for (int j = 0; j < PPB; j++) {
        const int p = psplit * PPB + j;
        const int w = sPW[p], v = sPV[p];
        const int off2 = sOF[p] >> 1;             // ull2 units (off even)
        const float P0 = sXs[b0 * 17 + w] * sXs[b0 * 17 + v];
        const float P1 = sXs[b1 * 17 + w] * sXs[b1 * 17 + v];
        ull ya0 = 0ull, ya1 = 0ull;
        const ull* s2p = sS2 + p;
        switch (sM[p]) {
            case 4: dot_block<4>(sS3u2, off2, s2p, sYs, bg, xp0, xp1, ya0, ya1); break;
            case 3: dot_block<3>(sS3u2, off2, s2p, sYs, bg, xp0, xp1, ya0, ya1); break;
            case 2: dot_block<2>(sS3u2, off2, s2p, sYs, bg, xp0, xp1, ya0, ya1); break;
            default: dot_block<1>(sS3u2, off2, s2p, sYs, bg, xp0, xp1, ya0, ya1); break;
        }
        acc0 = fma2(dup2(P0), ya0, acc0);
        acc1 = fma2(dup2(P1), ya1, acc1);
    }

    float lo, hi;
    float s0, s1;
    upk2(acc0, lo, hi); s0 = lo + hi;
    upk2(acc1, lo, hi); s1 = lo + hi;

    // ---- nu=1 (psplit 0 only) ----
    if (psplit == 0) {
        const float* v1 = V1g + c * V1_PER_C;
        float add0 = 0.f, add1 = 0.f;
#pragma unroll 1
        for (int e = 0; e < EDIM; e++) {
            float t0 = 0.f, t1 = 0.f;
#pragma unroll
            for (int w = 0; w < 16; w++) {
                const float vv = v1[e * 16 + w];
                t0 = fmaf(vv, sXs[b0 * 17 + w], t0);
                t1 = fmaf(vv, sXs[b1 * 17 + w], t1);
            }
            add0 = fmaf(sYs[e * 256 + b0], t0, add0);
            add1 = fmaf(sYs[e * 256 + b1], t1, add1);
        }
        s0 += add0; s1 += add1;
    }

    // ---- deterministic cross-split reduction ----
    red[psplit * 256 + b0] = s0;
    red[psplit * 256 + b1] = s1;
    __syncthreads();
    if (tid < 256) {
        float s = 0.f;
#pragma unroll
        for (int k = 0; k < 8; k++) s += red[k * 256 + tid];
        out[(base + tid) * CDIM + c] = s;
    }
}

// ---- launch --------------------------------------------------------------------
extern "C" void kernel_launch(void* const* d_in, const int* in_sizes, int n_in,
                              void* d_out, int out_size) {
    const float* x  = (const float*)d_in[0];
    const float* y  = (const float*)d_in[1];
    const float* U3 = (const float*)d_in[2];
    const float* U2 = (const float*)d_in[3];
    const float* U1 = (const float*)d_in[4];
    const float* W3 = (const float*)d_in[5];
    const float* W2 = (const float*)d_in[6];
    const float* W1 = (const float*)d_in[7];
    float* out = (float*)d_out;

    cudaFuncSetAttribute(k_s3, cudaFuncAttributeMaxDynamicSharedMemorySize, SMEM_KS3);
    cudaFuncSetAttribute(sc_main, cudaFuncAttributeMaxDynamicSharedMemorySize, SMEM_MAIN);

    k_tab<<<1, 256>>>();
    k_sym<<<(K3C * NSLOT_F + 255) / 256, 256>>>(U3);
    k_s3<<<CDIM, 512, SMEM_KS3>>>(W3, U2, W2, U1, W1);

    dim3 grid(CDIM, BDIM / 256);
    sc_main<<<grid, 1024, SMEM_MAIN>>>(x, y, out);
}

// round 9
// speedup vs baseline: 1.0015x; 1.0015x over previous
#include <cuda_runtime.h>
#include <cstdint>

// ---------------------------------------------------------------------------
// out[b,c] = sum_e y[b,e]*( sum_{w<=v<=i} S3[c,e,(w,v,i)] x_w x_v x_i
//                         + sum_{w<=v}    S2[c,e,(w,v)]   x_w x_v
//                         + sum_w         V1[c,e,w]       x_w )
// Round 7: 2 b's/thread @ 1024 threads (occ 25->50%), LDS.128 S3 streams
// (even-padded pair lengths), scalar y.
// ---------------------------------------------------------------------------

namespace {
constexpr int LDIM = 16;
constexpr int EDIM = 10;
constexpr int CDIM = 256;
constexpr int BDIM = 1024;
constexpr int K3C  = 23;
constexpr int K2C  = 4;

constexpr int NPAIR    = 136;           // (w<=v) pairs, 8 buckets x 17
constexpr int NBUCK    = 8;
constexpr int PPB      = 17;
constexpr int BSTRIDE  = 72;            // ull slots per bucket (even-padded, max 68)
constexpr int NSLOT_U  = NBUCK * BSTRIDE;   // 576 ull per e
constexpr int NSLOT_U2 = NSLOT_U / 2;       // 288 ull2 per e
constexpr int NSLOT_F  = 2 * NSLOT_U;       // 1152 floats per e

constexpr int S3_PER_C  = EDIM * NSLOT_F;   // 11520 floats
constexpr int S2U_PER_C = EDIM * NPAIR;     // 1360 ull
constexpr int V1_PER_C  = EDIM * LDIM;      // 160

constexpr int SMEM_MAIN =
    S3_PER_C * 4 +        // 46080
    S2U_PER_C * 8 +       // 10880
    256 * 17 * 4 +        // 17408 x scalars, stride 17
    EDIM * 256 * 4 +      // 10240 scalar y [e][b]
    NPAIR * 4 * 4 +       //  2176 tables (w,v,off,M)
    8 * 256 * 4;          //  8192 reduction
// = 94976

constexpr int SMEM_KS3 = (K3C * NSLOT_F + EDIM * K3C + 8) * 4;  // ~107 KB
}

// ---- device scratch ----------------------------------------------------------
__device__ int   g_pw[NPAIR], g_pv[NPAIR], g_off[NPAIR], g_m[NPAIR];
__device__ int   g_s2p[NSLOT_F], g_s2i[NSLOT_F];   // float-slot -> pair, i
__device__ float U3symT[K3C * NSLOT_F];            // [k][slot], zero-padded
__device__ float S3g[CDIM * S3_PER_C];             // ~11.8 MB
__device__ unsigned long long S2gu[CDIM * S2U_PER_C];
__device__ float V1g[CDIM * V1_PER_C];

// ---- packed f32x2 helpers (sm_103a) -------------------------------------------
using ull = unsigned long long;
__device__ __forceinline__ ull pk2(float a, float b) {
    ull r;
    asm("mov.b64 %0, {%1, %2};"
        : "=l"(r) : "r"(__float_as_uint(a)), "r"(__float_as_uint(b)));
    return r;
}
__device__ __forceinline__ ull dup2(float a) {
    ull r;
    asm("mov.b64 %0, {%1, %1};" : "=l"(r) : "r"(__float_as_uint(a)));
    return r;
}
__device__ __forceinline__ ull fma2(ull a, ull b, ull c) {
    ull d;
    asm("fma.rn.f32x2 %0, %1, %2, %3;" : "=l"(d) : "l"(a), "l"(b), "l"(c));
    return d;
}
__device__ __forceinline__ void upk2(ull v, float& a, float& b) {
    unsigned int lo, hi;
    asm("mov.b64 {%0, %1}, %2;" : "=r"(lo), "=r"(hi) : "l"(v));
    a = __uint_as_float(lo);
    b = __uint_as_float(hi);
}

// ---- k_tab: parallel table builder, balanced buckets, EVEN-padded lengths -----
__device__ __forceinline__ int len_of_rank(int r) {
    int o = 0, L = 8;
    while (L > 1 && o + 4 * (8 - L) + 3 <= r) { o += 4 * (8 - L) + 3; L--; }
    return L;
}
__global__ void k_tab() {
    const int tid = threadIdx.x;
    for (int s = tid; s < NSLOT_F; s += 256) { g_s2i[s] = -1; g_s2p[s] = 0; }
    __syncthreads();
    if (tid >= NPAIR) return;

    int p = tid, w = 0;
    while (p >= LDIM - w) { p -= LDIM - w; w++; }
    const int v = w + p;
    const int g = v >> 1;
    const int L = 8 - g;

    int idx = 0;
    for (int w2 = 0; w2 < w; w2++) {
        if (2 * g     >= w2) idx++;
        if (2 * g + 1 >= w2) idx++;
    }
    if ((v & 1) && (2 * g >= w)) idx++;
    int offL = 0;
    for (int L2 = 8; L2 > L; L2--) offL += 4 * (8 - L2) + 3;
    const int rank   = offL + idx;
    const int bucket = rank & 7;
    const int j      = rank >> 3;

    // offsets use ceil-to-even lengths (16B alignment for LDS.128)
    int off_local = 0;
    for (int j2 = 0; j2 < j; j2++) {
        const int L2 = len_of_rank(j2 * 8 + bucket);
        off_local += (L2 + 1) & ~1;
    }

    const int off_abs = bucket * BSTRIDE + off_local;   // even
    const int pi = bucket * PPB + j;
    g_pw[pi]  = w;
    g_pv[pi]  = v;
    g_off[pi] = off_abs;
    g_m[pi]   = (L + 1) >> 1;   // ull2 count

    for (int u = 0; u < L; u++)
        for (int r = 0; r < 2; r++) {
            const int s = 2 * (off_abs + u) + r;
            const int i = 14 - 2 * u + r;
            g_s2p[s] = pi;
            g_s2i[s] = (i >= v) ? i : -1;
        }
    // padding slots (u in [L, 2*M)) stay -1 -> zeros in U3symT/S3g
}

// ---- k_sym: symmetrized U3, transposed [k][slot] ------------------------------
__device__ __forceinline__ float u3at(const float* U3, int a, int b, int c, int k) {
    return U3[((a * 16 + b) * 16 + c) * K3C + k];
}
__global__ void k_sym(const float* __restrict__ U3) {
    const int idx = blockIdx.x * 256 + threadIdx.x;   // 23 * 1152
    if (idx >= K3C * NSLOT_F) return;
    const int s = idx % NSLOT_F;
    const int k = idx / NSLOT_F;
    const int i = g_s2i[s];
    float val = 0.f;
    if (i >= 0) {
        const int pi = g_s2p[s];
        const int w = g_pw[pi], v = g_pv[pi];
        if (w == v && v == i) {
            val = u3at(U3, w, w, w, k);
        } else if (w == v) {
            val = u3at(U3, w, w, i, k) + u3at(U3, w, i, w, k) + u3at(U3, i, w, w, k);
        } else if (v == i) {
            val = u3at(U3, w, v, v, k) + u3at(U3, v, w, v, k) + u3at(U3, v, v, w, k);
        } else {
            val = u3at(U3, w, v, i, k) + u3at(U3, w, i, v, k) +
                  u3at(U3, v, w, i, k) + u3at(U3, v, i, w, k) +
                  u3at(U3, i, w, v, k) + u3at(U3, i, v, w, k);
        }
    }
    U3symT[k * NSLOT_F + s] = val;
}

// ---- k_s3: per-c contraction + fused S2/V1 ------------------------------------
__global__ __launch_bounds__(512, 1)
void k_s3(const float* __restrict__ W3, const float* __restrict__ U2,
          const float* __restrict__ W2, const float* __restrict__ U1,
          const float* __restrict__ W1) {
    extern __shared__ float sm[];
    float* sU = sm;                       // [23][1152]
    float* sW = sm + K3C * NSLOT_F;       // [10][23]
    const int tid = threadIdx.x;
    const int c   = blockIdx.x;

    for (int t = tid; t < K3C * NSLOT_F; t += 512) sU[t] = U3symT[t];
    if (tid < EDIM * K3C) {
        const int e = tid / K3C, k = tid - e * K3C;
        sW[tid] = W3[(e * K3C + k) * CDIM + c];
    }
    __syncthreads();

#pragma unroll 1
    for (int idx = tid; idx < S3_PER_C; idx += 512) {
        const int e = idx / NSLOT_F;
        const int s = idx - e * NSLOT_F;
        float a = 0.f;
#pragma unroll
        for (int k = 0; k < K3C; k++)
            a = fmaf(sU[k * NSLOT_F + s], sW[e * K3C + k], a);
        S3g[c * S3_PER_C + idx] = a;
    }

    for (int t = tid; t < S2U_PER_C; t += 512) {
        const int e = t / NPAIR, pp = t - e * NPAIR;
        const int w = g_pw[pp], v = g_pv[pp];
        float s = 0.f;
#pragma unroll
        for (int k = 0; k < K2C; k++) {
            float u = U2[(w * 16 + v) * K2C + k];
            if (w != v) u += U2[(v * 16 + w) * K2C + k];
            s = fmaf(u, W2[(e * K2C + k) * CDIM + c], s);
        }
        S2gu[c * S2U_PER_C + t] = (ull)__float_as_uint(s);  // (s, 0)
    }
    if (tid < V1_PER_C) {
        const int e = tid >> 4, w = tid & 15;
        V1g[c * V1_PER_C + tid] = U1[w] * W1[e * CDIM + c];
    }
}

// ---- sc_main: single-pair dot, ulonglong2 stream loads, 2 b's/thread -----------
template <int M>
__device__ __forceinline__ void dot_block(
    const ulonglong2* __restrict__ sS3u2, int off2, const ull* __restrict__ s2p,
    const float* __restrict__ sYs, int bg,
    const ull (&xp0)[8], const ull (&xp1)[8],
    ull& ya0, ull& ya1)
{
#pragma unroll 1
    for (int e = 0; e < EDIM; e++) {
        const ulonglong2* st = sS3u2 + e * NSLOT_U2 + off2;
        const ull s2 = s2p[e * NPAIR];
        ull d0 = s2, d1 = s2;
#pragma unroll
        for (int m = 0; m < M; m++) {
            const ulonglong2 t = st[m];            // LDS.128 broadcast
            d0 = fma2(t.x, xp0[7 - 2 * m], d0);
            d1 = fma2(t.x, xp1[7 - 2 * m], d1);
            d0 = fma2(t.y, xp0[6 - 2 * m], d0);
            d1 = fma2(t.y, xp1[6 - 2 * m], d1);
        }
        const float* yrow = sYs + e * 256;
        ya0 = fma2(d0, dup2(yrow[bg]), ya0);
        ya1 = fma2(d1, dup2(yrow[bg + 128]), ya1);
    }
}

// Grid (c=256, btile=4). 1024 threads: bg = tid&127 owns b's {bg, bg+128};
// psplit = tid>>7 owns one balanced bucket of 17 pairs.
__global__ __launch_bounds__(1024, 1)
void sc_main(const float* __restrict__ x, const float* __restrict__ y,
             float* __restrict__ out) {
    extern __shared__ char smraw[];
    float* sS3 = reinterpret_cast<float*>(smraw);
    ull*   sS2 = reinterpret_cast<ull*>(sS3 + S3_PER_C);
    float* sXs = reinterpret_cast<float*>(sS2 + S2U_PER_C);
    float* sYs = sXs + 256 * 17;
    int*   sPW = reinterpret_cast<int*>(sYs + EDIM * 256);
    int*   sPV = sPW + NPAIR;
    int*   sOF = sPV + NPAIR;
    int*   sM  = sOF + NPAIR;
    float* red = reinterpret_cast<float*>(sM + NPAIR);
    const ulonglong2* sS3u2 = reinterpret_cast<const ulonglong2*>(sS3);

    const int tid    = threadIdx.x;
    const int c      = blockIdx.x;
    const int base   = blockIdx.y * 256;
    const int bg     = tid & 127;
    const int psplit = tid >> 7;

    // ---- stage S3 / S2 (coalesced) ----
    {
        const float4* src = reinterpret_cast<const float4*>(S3g + c * S3_PER_C);
        float4* dst = reinterpret_cast<float4*>(sS3);
        for (int t = tid; t < S3_PER_C / 4; t += 1024) dst[t] = src[t];
        for (int t = tid; t < S2U_PER_C; t += 1024)
            sS2[t] = S2gu[c * S2U_PER_C + t];
    }
    // ---- stage x scalars ----
#pragma unroll
    for (int t = 0; t < 4; t++) {
        const int idx = tid + t * 1024;           // 4096 = 256*16
        const int b = idx >> 4, i = idx & 15;
        sXs[b * 17 + i] = x[((base + b) * CDIM + c) * LDIM + i];
    }
    // ---- stage scalar y [e][b] ----
    for (int idx = tid; idx < EDIM * 256; idx += 1024) {
        const int b = idx & 255, e = idx >> 8;
        sYs[e * 256 + b] = y[(base + b) * EDIM + e];
    }
    if (tid < NPAIR) {
        sPW[tid] = g_pw[tid];
        sPV[tid] = g_pv[tid];
        sOF[tid] = g_off[tid];
        sM[tid]  = g_m[tid];
    }
    __syncthreads();

    // ---- per-thread packed x (2 b's) ----
    const int b0 = bg, b1 = bg + 128;
    ull xp0[8], xp1[8];
#pragma unroll
    for (int q = 0; q < 8; q++) {
        xp0[q] = pk2(sXs[b0 * 17 + 2 * q], sXs[b0 * 17 + 2 * q + 1]);
        xp1[q] = pk2(sXs[b1 * 17 + 2 * q], sXs[b1 * 17 + 2 * q + 1]);
    }

    ull acc0 = 0ull, acc1 = 0ull;

#pragma unroll 1
    for (int j = 0; j < PPB; j++) {
        const int p = psplit * PPB + j;
        const int w = sPW[p], v = sPV[p];
        const int off2 = sOF[p] >> 1;             // ull2 units (off even)
        const float P0 = sXs[b0 * 17 + w] * sXs[b0 * 17 + v];
        const float P1 = sXs[b1 * 17 + w] * sXs[b1 * 17 + v];
        ull ya0 = 0ull, ya1 = 0ull;
        const ull* s2p = sS2 + p;
        switch (sM[p]) {
            case 4: dot_block<4>(sS3u2, off2, s2p, sYs, bg, xp0, xp1, ya0, ya1); break;
            case 3: dot_block<3>(sS3u2, off2, s2p, sYs, bg, xp0, xp1, ya0, ya1); break;
            case 2: dot_block<2>(sS3u2, off2, s2p, sYs, bg, xp0, xp1, ya0, ya1); break;
            default: dot_block<1>(sS3u2, off2, s2p, sYs, bg, xp0, xp1, ya0, ya1); break;
        }
        acc0 = fma2(dup2(P0), ya0, acc0);
        acc1 = fma2(dup2(P1), ya1, acc1);
    }

    float lo, hi;
    float s0, s1;
    upk2(acc0, lo, hi); s0 = lo + hi;
    upk2(acc1, lo, hi); s1 = lo + hi;

    // ---- nu=1 (psplit 0 only) ----
    if (psplit == 0) {
        const float* v1 = V1g + c * V1_PER_C;
        float add0 = 0.f, add1 = 0.f;
#pragma unroll 1
        for (int e = 0; e < EDIM; e++) {
            float t0 = 0.f, t1 = 0.f;
#pragma unroll
            for (int w = 0; w < 16; w++) {
                const float vv = v1[e * 16 + w];
                t0 = fmaf(vv, sXs[b0 * 17 + w], t0);
                t1 = fmaf(vv, sXs[b1 * 17 + w], t1);
            }
            add0 = fmaf(sYs[e * 256 + b0], t0, add0);
            add1 = fmaf(sYs[e * 256 + b1], t1, add1);
        }
        s0 += add0; s1 += add1;
    }

    // ---- deterministic cross-split reduction ----
    red[psplit * 256 + b0] = s0;
    red[psplit * 256 + b1] = s1;
    __syncthreads();
    if (tid < 256) {
        float s = 0.f;
#pragma unroll
        for (int k = 0; k < 8; k++) s += red[k * 256 + tid];
        out[(base + tid) * CDIM + c] = s;
    }
}

// ---- launch --------------------------------------------------------------------
extern "C" void kernel_launch(void* const* d_in, const int* in_sizes, int n_in,
                              void* d_out, int out_size) {
    const float* x  = (const float*)d_in[0];
    const float* y  = (const float*)d_in[1];
    const float* U3 = (const float*)d_in[2];
    const float* U2 = (const float*)d_in[3];
    const float* U1 = (const float*)d_in[4];
    const float* W3 = (const float*)d_in[5];
    const float* W2 = (const float*)d_in[6];
    const float* W1 = (const float*)d_in[7];
    float* out = (float*)d_out;

    cudaFuncSetAttribute(k_s3, cudaFuncAttributeMaxDynamicSharedMemorySize, SMEM_KS3);
    cudaFuncSetAttribute(sc_main, cudaFuncAttributeMaxDynamicSharedMemorySize, SMEM_MAIN);

    k_tab<<<1, 256>>>();
    k_sym<<<(K3C * NSLOT_F + 255) / 256, 256>>>(U3);
    k_s3<<<CDIM, 512, SMEM_KS3>>>(W3, U2, W2, U1, W1);

    dim3 grid(CDIM, BDIM / 256);
    sc_main<<<grid, 1024, SMEM_MAIN>>>(x, y, out);
}

// round 11
// speedup vs baseline: 1.2758x; 1.2739x over previous
#include <cuda_runtime.h>
#include <cstdint>

// ---------------------------------------------------------------------------
// out[b,c] = sum_e y[b,e]*( sum_{w<=v<=i} S3[c,e,(w,v,i)] x_w x_v x_i
//                         + sum_{w<=v}    S2[c,e,(w,v)]   x_w x_v
//                         + sum_w         V1[c,e,w]       x_w )
// Round 11: round-10 design with __host__ __device__ constexpr annotations
// (fixes nvcc "host constexpr from device" errors). Bucket-templated pair
// loop, compile-time w/v/len/offsets, LDS.128 streams, 512 thr / 4 b per thr.
// ---------------------------------------------------------------------------

namespace {
constexpr int LDIM = 16;
constexpr int EDIM = 10;
constexpr int CDIM = 256;
constexpr int BDIM = 1024;
constexpr int K3C  = 23;
constexpr int K2C  = 4;

constexpr int NPAIR    = 136;           // (w<=v) pairs, 8 buckets x 17
constexpr int NBUCK    = 8;
constexpr int PPB      = 17;
constexpr int BSTRIDE  = 72;            // ull slots per bucket (even-padded)
constexpr int NSLOT_U  = NBUCK * BSTRIDE;   // 576 ull per e
constexpr int NSLOT_U2 = NSLOT_U / 2;       // 288 ull2 per e
constexpr int NSLOT_F  = 2 * NSLOT_U;       // 1152 floats per e

constexpr int S3_PER_C  = EDIM * NSLOT_F;   // 11520 floats
constexpr int S2U_PER_C = EDIM * NPAIR;     // 1360 ull
constexpr int V1_PER_C  = EDIM * LDIM;      // 160

constexpr int SMEM_MAIN =
    S3_PER_C * 4 +        // 46080
    S2U_PER_C * 8 +       // 10880
    256 * 17 * 4 +        // 17408 x scalars, stride 17
    EDIM * 256 * 4 +      // 10240 scalar y [e][b]
    8 * 256 * 4;          //  8192 reduction
// = 92800

constexpr int SMEM_KS3 = (K3C * NSLOT_F + EDIM * K3C + 8) * 4;  // ~107 KB

// ---- compile-time pair schedule (device-usable constexpr) -------------------
// class g = v>>1 has cnt 4g+3 pairs; ranks sorted by len desc (g asc).
__host__ __device__ constexpr int class_start(int g) {
    int s = 0;
    for (int g2 = 0; g2 < g; g2++) s += 4 * g2 + 3;
    return s;
}
__host__ __device__ constexpr int rank_g(int r) {
    int g = 0;
    while (g < 7 && class_start(g + 1) <= r) g++;
    return g;
}
__host__ __device__ constexpr int rank_len(int r) { return 8 - rank_g(r); }
__host__ __device__ constexpr int pr_w(int r) {
    const int g = rank_g(r), idx = r - class_start(g);
    return idx < 4 * g + 2 ? (idx >> 1) : (2 * g + 1);
}
__host__ __device__ constexpr int pr_v(int r) {
    const int g = rank_g(r), idx = r - class_start(g);
    return idx < 4 * g + 2 ? (2 * g + (idx & 1)) : (2 * g + 1);
}
// ull2 offset of bucket B, slot J (even-padded lengths), in ull2 units
__host__ __device__ constexpr int boff2(int B, int J) {
    int o = 0;
    for (int j = 0; j < J; j++) o += (rank_len(j * 8 + B) + 1) / 2;
    return B * (BSTRIDE / 2) + o;
}
}

// ---- device scratch ----------------------------------------------------------
__device__ int   g_pw[NPAIR], g_pv[NPAIR];
__device__ int   g_s2p[NSLOT_F], g_s2i[NSLOT_F];   // float-slot -> pair, i
__device__ float U3symT[K3C * NSLOT_F];            // [k][slot], zero-padded
__device__ float S3g[CDIM * S3_PER_C];             // ~11.8 MB
__device__ unsigned long long S2gu[CDIM * S2U_PER_C];
__device__ float V1g[CDIM * V1_PER_C];

// ---- packed f32x2 helpers (sm_103a) -------------------------------------------
using ull = unsigned long long;
__device__ __forceinline__ ull pk2(float a, float b) {
    ull r;
    asm("mov.b64 %0, {%1, %2};"
        : "=l"(r) : "r"(__float_as_uint(a)), "r"(__float_as_uint(b)));
    return r;
}
__device__ __forceinline__ ull dup2(float a) {
    ull r;
    asm("mov.b64 %0, {%1, %1};" : "=l"(r) : "r"(__float_as_uint(a)));
    return r;
}
__device__ __forceinline__ ull fma2(ull a, ull b, ull c) {
    ull d;
    asm("fma.rn.f32x2 %0, %1, %2, %3;" : "=l"(d) : "l"(a), "l"(b), "l"(c));
    return d;
}
__device__ __forceinline__ void upk2(ull v, float& a, float& b) {
    unsigned int lo, hi;
    asm("mov.b64 {%0, %1}, %2;" : "=r"(lo), "=r"(hi) : "l"(v));
    a = __uint_as_float(lo);
    b = __uint_as_float(hi);
}

// ---- k_tab: runtime twin of the constexpr schedule (feeds k_sym/k_s3) --------
__global__ void k_tab() {
    const int tid = threadIdx.x;
    for (int s = tid; s < NSLOT_F; s += 256) { g_s2i[s] = -1; g_s2p[s] = 0; }
    __syncthreads();
    if (tid >= NPAIR) return;

    const int B = tid & 7;        // bucket
    const int J = tid >> 3;       // slot in bucket
    const int rank = J * 8 + B;
    const int w = pr_w(rank);
    const int v = pr_v(rank);
    const int L = rank_len(rank);
    const int off_abs = boff2(B, J) * 2;   // ull units
    const int pi = B * PPB + J;

    g_pw[pi] = w;
    g_pv[pi] = v;

    for (int u = 0; u < L; u++)
        for (int r = 0; r < 2; r++) {
            const int s = 2 * (off_abs + u) + r;
            const int i = 14 - 2 * u + r;
            g_s2p[s] = pi;
            g_s2i[s] = (i >= v) ? i : -1;
        }
}

// ---- k_sym: symmetrized U3, transposed [k][slot] ------------------------------
__device__ __forceinline__ float u3at(const float* U3, int a, int b, int c, int k) {
    return U3[((a * 16 + b) * 16 + c) * K3C + k];
}
__global__ void k_sym(const float* __restrict__ U3) {
    const int idx = blockIdx.x * 256 + threadIdx.x;   // 23 * 1152
    if (idx >= K3C * NSLOT_F) return;
    const int s = idx % NSLOT_F;
    const int k = idx / NSLOT_F;
    const int i = g_s2i[s];
    float val = 0.f;
    if (i >= 0) {
        const int pi = g_s2p[s];
        const int w = g_pw[pi], v = g_pv[pi];
        if (w == v && v == i) {
            val = u3at(U3, w, w, w, k);
        } else if (w == v) {
            val = u3at(U3, w, w, i, k) + u3at(U3, w, i, w, k) + u3at(U3, i, w, w, k);
        } else if (v == i) {
            val = u3at(U3, w, v, v, k) + u3at(U3, v, w, v, k) + u3at(U3, v, v, w, k);
        } else {
            val = u3at(U3, w, v, i, k) + u3at(U3, w, i, v, k) +
                  u3at(U3, v, w, i, k) + u3at(U3, v, i, w, k) +
                  u3at(U3, i, w, v, k) + u3at(U3, i, v, w, k);
        }
    }
    U3symT[k * NSLOT_F + s] = val;
}

// ---- k_s3: per-c contraction + fused S2/V1 ------------------------------------
__global__ __launch_bounds__(512, 1)
void k_s3(const float* __restrict__ W3, const float* __restrict__ U2,
          const float* __restrict__ W2, const float* __restrict__ U1,
          const float* __restrict__ W1) {
    extern __shared__ float sm[];
    float* sU = sm;                       // [23][1152]
    float* sW = sm + K3C * NSLOT_F;       // [10][23]
    const int tid = threadIdx.x;
    const int c   = blockIdx.x;

    for (int t = tid; t < K3C * NSLOT_F; t += 512) sU[t] = U3symT[t];
    if (tid < EDIM * K3C) {
        const int e = tid / K3C, k = tid - e * K3C;
        sW[tid] = W3[(e * K3C + k) * CDIM + c];
    }
    __syncthreads();

#pragma unroll 1
    for (int idx = tid; idx < S3_PER_C; idx += 512) {
        const int e = idx / NSLOT_F;
        const int s = idx - e * NSLOT_F;
        float a = 0.f;
#pragma unroll
        for (int k = 0; k < K3C; k++)
            a = fmaf(sU[k * NSLOT_F + s], sW[e * K3C + k], a);
        S3g[c * S3_PER_C + idx] = a;
    }

    for (int t = tid; t < S2U_PER_C; t += 512) {
        const int e = t / NPAIR, pp = t - e * NPAIR;
        const int w = g_pw[pp], v = g_pv[pp];
        float s = 0.f;
#pragma unroll
        for (int k = 0; k < K2C; k++) {
            float u = U2[(w * 16 + v) * K2C + k];
            if (w != v) u += U2[(v * 16 + w) * K2C + k];
            s = fmaf(u, W2[(e * K2C + k) * CDIM + c], s);
        }
        S2gu[c * S2U_PER_C + t] = (ull)__float_as_uint(s);  // (s, 0)
    }
    if (tid < V1_PER_C) {
        const int e = tid >> 4, w = tid & 15;
        V1g[c * V1_PER_C + tid] = U1[w] * W1[e * CDIM + c];
    }
}

// ---- sc_main: templated dot over e, LDS.128 streams, 4 b's/thread --------------
template <int M>
__device__ __forceinline__ void dot_block(
    const ulonglong2* __restrict__ st0, const ull* __restrict__ s2p,
    const float* __restrict__ sYs, int bg,
    const ull (&xp0)[8], const ull (&xp1)[8], const ull (&xp2)[8], const ull (&xp3)[8],
    ull& ya0, ull& ya1, ull& ya2, ull& ya3)
{
#pragma unroll 1
    for (int e = 0; e < EDIM; e++) {
        const ulonglong2* st = st0 + e * NSLOT_U2;
        const ull s2 = s2p[e * NPAIR];
        ull d0 = s2, d1 = s2, d2 = s2, d3 = s2;
#pragma unroll
        for (int m = 0; m < M; m++) {
            const ulonglong2 t = st[m];            // LDS.128 broadcast
            d0 = fma2(t.x, xp0[7 - 2 * m], d0);
            d1 = fma2(t.x, xp1[7 - 2 * m], d1);
            d2 = fma2(t.x, xp2[7 - 2 * m], d2);
            d3 = fma2(t.x, xp3[7 - 2 * m], d3);
            d0 = fma2(t.y, xp0[6 - 2 * m], d0);
            d1 = fma2(t.y, xp1[6 - 2 * m], d1);
            d2 = fma2(t.y, xp2[6 - 2 * m], d2);
            d3 = fma2(t.y, xp3[6 - 2 * m], d3);
        }
        const float* yrow = sYs + e * 256;
        ya0 = fma2(d0, dup2(yrow[bg]), ya0);
        ya1 = fma2(d1, dup2(yrow[bg + 64]), ya1);
        ya2 = fma2(d2, dup2(yrow[bg + 128]), ya2);
        ya3 = fma2(d3, dup2(yrow[bg + 192]), ya3);
    }
}

// Recursive fully-unrolled pair chain for bucket B: all (w,v,M,off,p) constexpr.
template <int B, int J>
struct PairChain {
    static __device__ __forceinline__ void run(
        const ulonglong2* __restrict__ sS3u2, const ull* __restrict__ sS2,
        const float* __restrict__ sXs, const float* __restrict__ sYs,
        int bg, int b0, int b1, int b2, int b3,
        const ull (&xp0)[8], const ull (&xp1)[8], const ull (&xp2)[8], const ull (&xp3)[8],
        ull& acc0, ull& acc1, ull& acc2, ull& acc3)
    {
        constexpr int rank = J * 8 + B;
        constexpr int w    = pr_w(rank);
        constexpr int v    = pr_v(rank);
        constexpr int M    = (rank_len(rank) + 1) / 2;
        constexpr int off2 = boff2(B, J);
        constexpr int p    = B * PPB + J;

        const float P0 = sXs[b0 * 17 + w] * sXs[b0 * 17 + v];
        const float P1 = sXs[b1 * 17 + w] * sXs[b1 * 17 + v];
        const float P2 = sXs[b2 * 17 + w] * sXs[b2 * 17 + v];
        const float P3 = sXs[b3 * 17 + w] * sXs[b3 * 17 + v];
        ull ya0 = 0ull, ya1 = 0ull, ya2 = 0ull, ya3 = 0ull;
        dot_block<M>(sS3u2 + off2, sS2 + p, sYs, bg, xp0, xp1, xp2, xp3,
                     ya0, ya1, ya2, ya3);
        acc0 = fma2(dup2(P0), ya0, acc0);
        acc1 = fma2(dup2(P1), ya1, acc1);
        acc2 = fma2(dup2(P2), ya2, acc2);
        acc3 = fma2(dup2(P3), ya3, acc3);

        PairChain<B, J + 1>::run(sS3u2, sS2, sXs, sYs, bg, b0, b1, b2, b3,
                                 xp0, xp1, xp2, xp3, acc0, acc1, acc2, acc3);
    }
};
template <int B>
struct PairChain<B, PPB> {
    static __device__ __forceinline__ void run(
        const ulonglong2*, const ull*, const float*, const float*,
        int, int, int, int, int,
        const ull (&)[8], const ull (&)[8], const ull (&)[8], const ull (&)[8],
        ull&, ull&, ull&, ull&) {}
};

// Grid (c=256, btile=4). 512 threads: bg = tid&63 owns 4 b's; psplit = tid>>6
// owns one bucket (compile-time schedule). Lanes carry (even-i, odd-i).
__global__ __launch_bounds__(512, 1)
void sc_main(const float* __restrict__ x, const float* __restrict__ y,
             float* __restrict__ out) {
    extern __shared__ char smraw[];
    float* sS3 = reinterpret_cast<float*>(smraw);
    ull*   sS2 = reinterpret_cast<ull*>(sS3 + S3_PER_C);
    float* sXs = reinterpret_cast<float*>(sS2 + S2U_PER_C);
    float* sYs = sXs + 256 * 17;
    float* red = sYs + EDIM * 256;
    const ulonglong2* sS3u2 = reinterpret_cast<const ulonglong2*>(sS3);

    const int tid    = threadIdx.x;
    const int c      = blockIdx.x;
    const int base   = blockIdx.y * 256;
    const int bg     = tid & 63;
    const int psplit = tid >> 6;

    // ---- stage S3 / S2 (coalesced) ----
    {
        const float4* src = reinterpret_cast<const float4*>(S3g + c * S3_PER_C);
        float4* dst = reinterpret_cast<float4*>(sS3);
        for (int t = tid; t < S3_PER_C / 4; t += 512) dst[t] = src[t];
        for (int t = tid; t < S2U_PER_C; t += 512)
            sS2[t] = S2gu[c * S2U_PER_C + t];
    }
    // ---- stage x scalars ----
#pragma unroll
    for (int t = 0; t < 8; t++) {
        const int idx = tid + t * 512;            // 4096 = 256*16
        const int b = idx >> 4, i = idx & 15;
        sXs[b * 17 + i] = x[((base + b) * CDIM + c) * LDIM + i];
    }
    // ---- stage scalar y [e][b] ----
#pragma unroll
    for (int t = 0; t < 5; t++) {
        const int idx = tid + t * 512;            // 2560 = 10*256
        const int b = idx & 255, e = idx >> 8;
        sYs[e * 256 + b] = y[(base + b) * EDIM + e];
    }
    __syncthreads();

    // ---- per-thread packed x (4 b's) ----
    const int b0 = bg, b1 = bg + 64, b2 = bg + 128, b3 = bg + 192;
    ull xp0[8], xp1[8], xp2[8], xp3[8];
#pragma unroll
    for (int q = 0; q < 8; q++) {
        xp0[q] = pk2(sXs[b0 * 17 + 2 * q], sXs[b0 * 17 + 2 * q + 1]);
        xp1[q] = pk2(sXs[b1 * 17 + 2 * q], sXs[b1 * 17 + 2 * q + 1]);
        xp2[q] = pk2(sXs[b2 * 17 + 2 * q], sXs[b2 * 17 + 2 * q + 1]);
        xp3[q] = pk2(sXs[b3 * 17 + 2 * q], sXs[b3 * 17 + 2 * q + 1]);
    }

    ull acc0 = 0ull, acc1 = 0ull, acc2 = 0ull, acc3 = 0ull;

    // one warp-uniform dispatch; each bucket fully unrolled at compile time
    switch (psplit) {
        case 0: PairChain<0, 0>::run(sS3u2, sS2, sXs, sYs, bg, b0, b1, b2, b3, xp0, xp1, xp2, xp3, acc0, acc1, acc2, acc3); break;
        case 1: PairChain<1, 0>::run(sS3u2, sS2, sXs, sYs, bg, b0, b1, b2, b3, xp0, xp1, xp2, xp3, acc0, acc1, acc2, acc3); break;
        case 2: PairChain<2, 0>::run(sS3u2, sS2, sXs, sYs, bg, b0, b1, b2, b3, xp0, xp1, xp2, xp3, acc0, acc1, acc2, acc3); break;
        case 3: PairChain<3, 0>::run(sS3u2, sS2, sXs, sYs, bg, b0, b1, b2, b3, xp0, xp1, xp2, xp3, acc0, acc1, acc2, acc3); break;
        case 4: PairChain<4, 0>::run(sS3u2, sS2, sXs, sYs, bg, b0, b1, b2, b3, xp0, xp1, xp2, xp3, acc0, acc1, acc2, acc3); break;
        case 5: PairChain<5, 0>::run(sS3u2, sS2, sXs, sYs, bg, b0, b1, b2, b3, xp0, xp1, xp2, xp3, acc0, acc1, acc2, acc3); break;
        case 6: PairChain<6, 0>::run(sS3u2, sS2, sXs, sYs, bg, b0, b1, b2, b3, xp0, xp1, xp2, xp3, acc0, acc1, acc2, acc3); break;
        default: PairChain<7, 0>::run(sS3u2, sS2, sXs, sYs, bg, b0, b1, b2, b3, xp0, xp1, xp2, xp3, acc0, acc1, acc2, acc3); break;
    }

    float lo, hi;
    float s0, s1, s2v, s3v;
    upk2(acc0, lo, hi); s0  = lo + hi;
    upk2(acc1, lo, hi); s1  = lo + hi;
    upk2(acc2, lo, hi); s2v = lo + hi;
    upk2(acc3, lo, hi); s3v = lo + hi;

    // ---- nu=1 (psplit 0 only) ----
    if (psplit == 0) {
        const float* v1 = V1g + c * V1_PER_C;
        float add0 = 0.f, add1 = 0.f, add2 = 0.f, add3 = 0.f;
#pragma unroll 1
        for (int e = 0; e < EDIM; e++) {
            float t0 = 0.f, t1 = 0.f, t2 = 0.f, t3 = 0.f;
#pragma unroll
            for (int w = 0; w < 16; w++) {
                const float vv = v1[e * 16 + w];
                t0 = fmaf(vv, sXs[b0 * 17 + w], t0);
                t1 = fmaf(vv, sXs[b1 * 17 + w], t1);
                t2 = fmaf(vv, sXs[b2 * 17 + w], t2);
                t3 = fmaf(vv, sXs[b3 * 17 + w], t3);
            }
            add0 = fmaf(sYs[e * 256 + b0], t0, add0);
            add1 = fmaf(sYs[e * 256 + b1], t1, add1);
            add2 = fmaf(sYs[e * 256 + b2], t2, add2);
            add3 = fmaf(sYs[e * 256 + b3], t3, add3);
        }
        s0 += add0; s1 += add1; s2v += add2; s3v += add3;
    }

    // ---- deterministic cross-split reduction ----
    red[psplit * 256 + b0] = s0;
    red[psplit * 256 + b1] = s1;
    red[psplit * 256 + b2] = s2v;
    red[psplit * 256 + b3] = s3v;
    __syncthreads();
    if (tid < 256) {
        float s = 0.f;
#pragma unroll
        for (int k = 0; k < 8; k++) s += red[k * 256 + tid];
        out[(base + tid) * CDIM + c] = s;
    }
}

// ---- launch --------------------------------------------------------------------
extern "C" void kernel_launch(void* const* d_in, const int* in_sizes, int n_in,
                              void* d_out, int out_size) {
    const float* x  = (const float*)d_in[0];
    const float* y  = (const float*)d_in[1];
    const float* U3 = (const float*)d_in[2];
    const float* U2 = (const float*)d_in[3];
    const float* U1 = (const float*)d_in[4];
    const float* W3 = (const float*)d_in[5];
    const float* W2 = (const float*)d_in[6];
    const float* W1 = (const float*)d_in[7];
    float* out = (float*)d_out;

    cudaFuncSetAttribute(k_s3, cudaFuncAttributeMaxDynamicSharedMemorySize, SMEM_KS3);
    cudaFuncSetAttribute(sc_main, cudaFuncAttributeMaxDynamicSharedMemorySize, SMEM_MAIN);

    k_tab<<<1, 256>>>();
    k_sym<<<(K3C * NSLOT_F + 255) / 256, 256>>>(U3);
    k_s3<<<CDIM, 512, SMEM_KS3>>>(W3, U2, W2, U1, W1);

    dim3 grid(CDIM, BDIM / 256);
    sc_main<<<grid, 512, SMEM_MAIN>>>(x, y, out);
}

// round 12
// speedup vs baseline: 1.3141x; 1.0301x over previous
#include <cuda_runtime.h>
#include <cstdint>

// ---------------------------------------------------------------------------
// out[b,c] = sum_e y[b,e]*( sum_{w<=v<=i} S3[c,e,(w,v,i)] x_w x_v x_i
//                         + sum_{w<=v}    S2[c,e,(w,v)]   x_w x_v
//                         + sum_w         V1[c,e,w]       x_w )
// Round 12: float4 y loads (1 LDS.128 vs 4 LDS.32 per (pair,e)) + e-loop
// unroll-by-2 for within-thread MLP. Base: round-11 templated schedule.
// ---------------------------------------------------------------------------

namespace {
constexpr int LDIM = 16;
constexpr int EDIM = 10;
constexpr int CDIM = 256;
constexpr int BDIM = 1024;
constexpr int K3C  = 23;
constexpr int K2C  = 4;

constexpr int NPAIR    = 136;           // (w<=v) pairs, 8 buckets x 17
constexpr int NBUCK    = 8;
constexpr int PPB      = 17;
constexpr int BSTRIDE  = 72;            // ull slots per bucket (even-padded)
constexpr int NSLOT_U  = NBUCK * BSTRIDE;   // 576 ull per e
constexpr int NSLOT_U2 = NSLOT_U / 2;       // 288 ull2 per e
constexpr int NSLOT_F  = 2 * NSLOT_U;       // 1152 floats per e

constexpr int S3_PER_C  = EDIM * NSLOT_F;   // 11520 floats
constexpr int S2U_PER_C = EDIM * NPAIR;     // 1360 ull
constexpr int V1_PER_C  = EDIM * LDIM;      // 160

constexpr int SMEM_MAIN =
    S3_PER_C * 4 +        // 46080
    S2U_PER_C * 8 +       // 10880
    256 * 17 * 4 +        // 17408 x scalars, stride 17
    EDIM * 256 * 4 +      // 10240 y float4 [e][bg][4]
    8 * 256 * 4;          //  8192 reduction
// = 92800

constexpr int SMEM_KS3 = (K3C * NSLOT_F + EDIM * K3C + 8) * 4;  // ~107 KB

// ---- compile-time pair schedule (device-usable constexpr) -------------------
__host__ __device__ constexpr int class_start(int g) {
    int s = 0;
    for (int g2 = 0; g2 < g; g2++) s += 4 * g2 + 3;
    return s;
}
__host__ __device__ constexpr int rank_g(int r) {
    int g = 0;
    while (g < 7 && class_start(g + 1) <= r) g++;
    return g;
}
__host__ __device__ constexpr int rank_len(int r) { return 8 - rank_g(r); }
__host__ __device__ constexpr int pr_w(int r) {
    const int g = rank_g(r), idx = r - class_start(g);
    return idx < 4 * g + 2 ? (idx >> 1) : (2 * g + 1);
}
__host__ __device__ constexpr int pr_v(int r) {
    const int g = rank_g(r), idx = r - class_start(g);
    return idx < 4 * g + 2 ? (2 * g + (idx & 1)) : (2 * g + 1);
}
__host__ __device__ constexpr int boff2(int B, int J) {
    int o = 0;
    for (int j = 0; j < J; j++) o += (rank_len(j * 8 + B) + 1) / 2;
    return B * (BSTRIDE / 2) + o;
}
}

// ---- device scratch ----------------------------------------------------------
__device__ int   g_pw[NPAIR], g_pv[NPAIR];
__device__ int   g_s2p[NSLOT_F], g_s2i[NSLOT_F];   // float-slot -> pair, i
__device__ float U3symT[K3C * NSLOT_F];            // [k][slot], zero-padded
__device__ float S3g[CDIM * S3_PER_C];             // ~11.8 MB
__device__ unsigned long long S2gu[CDIM * S2U_PER_C];
__device__ float V1g[CDIM * V1_PER_C];

// ---- packed f32x2 helpers (sm_103a) -------------------------------------------
using ull = unsigned long long;
__device__ __forceinline__ ull pk2(float a, float b) {
    ull r;
    asm("mov.b64 %0, {%1, %2};"
        : "=l"(r) : "r"(__float_as_uint(a)), "r"(__float_as_uint(b)));
    return r;
}
__device__ __forceinline__ ull dup2(float a) {
    ull r;
    asm("mov.b64 %0, {%1, %1};" : "=l"(r) : "r"(__float_as_uint(a)));
    return r;
}
__device__ __forceinline__ ull fma2(ull a, ull b, ull c) {
    ull d;
    asm("fma.rn.f32x2 %0, %1, %2, %3;" : "=l"(d) : "l"(a), "l"(b), "l"(c));
    return d;
}
__device__ __forceinline__ void upk2(ull v, float& a, float& b) {
    unsigned int lo, hi;
    asm("mov.b64 {%0, %1}, %2;" : "=r"(lo), "=r"(hi) : "l"(v));
    a = __uint_as_float(lo);
    b = __uint_as_float(hi);
}

// ---- k_tab: runtime twin of the constexpr schedule ---------------------------
__global__ void k_tab() {
    const int tid = threadIdx.x;
    for (int s = tid; s < NSLOT_F; s += 256) { g_s2i[s] = -1; g_s2p[s] = 0; }
    __syncthreads();
    if (tid >= NPAIR) return;

    const int B = tid & 7;
    const int J = tid >> 3;
    const int rank = J * 8 + B;
    const int w = pr_w(rank);
    const int v = pr_v(rank);
    const int L = rank_len(rank);
    const int off_abs = boff2(B, J) * 2;   // ull units
    const int pi = B * PPB + J;

    g_pw[pi] = w;
    g_pv[pi] = v;

    for (int u = 0; u < L; u++)
        for (int r = 0; r < 2; r++) {
            const int s = 2 * (off_abs + u) + r;
            const int i = 14 - 2 * u + r;
            g_s2p[s] = pi;
            g_s2i[s] = (i >= v) ? i : -1;
        }
}

// ---- k_sym: symmetrized U3, transposed [k][slot] ------------------------------
__device__ __forceinline__ float u3at(const float* U3, int a, int b, int c, int k) {
    return U3[((a * 16 + b) * 16 + c) * K3C + k];
}
__global__ void k_sym(const float* __restrict__ U3) {
    const int idx = blockIdx.x * 256 + threadIdx.x;   // 23 * 1152
    if (idx >= K3C * NSLOT_F) return;
    const int s = idx % NSLOT_F;
    const int k = idx / NSLOT_F;
    const int i = g_s2i[s];
    float val = 0.f;
    if (i >= 0) {
        const int pi = g_s2p[s];
        const int w = g_pw[pi], v = g_pv[pi];
        if (w == v && v == i) {
            val = u3at(U3, w, w, w, k);
        } else if (w == v) {
            val = u3at(U3, w, w, i, k) + u3at(U3, w, i, w, k) + u3at(U3, i, w, w, k);
        } else if (v == i) {
            val = u3at(U3, w, v, v, k) + u3at(U3, v, w, v, k) + u3at(U3, v, v, w, k);
        } else {
            val = u3at(U3, w, v, i, k) + u3at(U3, w, i, v, k) +
                  u3at(U3, v, w, i, k) + u3at(U3, v, i, w, k) +
                  u3at(U3, i, w, v, k) + u3at(U3, i, v, w, k);
        }
    }
    U3symT[k * NSLOT_F + s] = val;
}

// ---- k_s3: per-c contraction + fused S2/V1 ------------------------------------
__global__ __launch_bounds__(512, 1)
void k_s3(const float* __restrict__ W3, const float* __restrict__ U2,
          const float* __restrict__ W2, const float* __restrict__ U1,
          const float* __restrict__ W1) {
    extern __shared__ float sm[];
    float* sU = sm;                       // [23][1152]
    float* sW = sm + K3C * NSLOT_F;       // [10][23]
    const int tid = threadIdx.x;
    const int c   = blockIdx.x;

    for (int t = tid; t < K3C * NSLOT_F; t += 512) sU[t] = U3symT[t];
    if (tid < EDIM * K3C) {
        const int e = tid / K3C, k = tid - e * K3C;
        sW[tid] = W3[(e * K3C + k) * CDIM + c];
    }
    __syncthreads();

#pragma unroll 1
    for (int idx = tid; idx < S3_PER_C; idx += 512) {
        const int e = idx / NSLOT_F;
        const int s = idx - e * NSLOT_F;
        float a = 0.f;
#pragma unroll
        for (int k = 0; k < K3C; k++)
            a = fmaf(sU[k * NSLOT_F + s], sW[e * K3C + k], a);
        S3g[c * S3_PER_C + idx] = a;
    }

    for (int t = tid; t < S2U_PER_C; t += 512) {
        const int e = t / NPAIR, pp = t - e * NPAIR;
        const int w = g_pw[pp], v = g_pv[pp];
        float s = 0.f;
#pragma unroll
        for (int k = 0; k < K2C; k++) {
            float u = U2[(w * 16 + v) * K2C + k];
            if (w != v) u += U2[(v * 16 + w) * K2C + k];
            s = fmaf(u, W2[(e * K2C + k) * CDIM + c], s);
        }
        S2gu[c * S2U_PER_C + t] = (ull)__float_as_uint(s);  // (s, 0)
    }
    if (tid < V1_PER_C) {
        const int e = tid >> 4, w = tid & 15;
        V1g[c * V1_PER_C + tid] = U1[w] * W1[e * CDIM + c];
    }
}

// ---- sc_main: dot with float4 y + e-unroll 2 -----------------------------------
template <int M>
__device__ __forceinline__ void dot_block(
    const ulonglong2* __restrict__ st0, const ull* __restrict__ s2p,
    const float4* __restrict__ sY4, int bg,
    const ull (&xp0)[8], const ull (&xp1)[8], const ull (&xp2)[8], const ull (&xp3)[8],
    ull& ya0, ull& ya1, ull& ya2, ull& ya3)
{
#pragma unroll 2
    for (int e = 0; e < EDIM; e++) {
        const ulonglong2* st = st0 + e * NSLOT_U2;
        const ull s2 = s2p[e * NPAIR];
        const float4 yv = sY4[e * 64 + bg];    // one LDS.128 per (pair,e)
        ull d0 = s2, d1 = s2, d2 = s2, d3 = s2;
#pragma unroll
        for (int m = 0; m < M; m++) {
            const ulonglong2 t = st[m];        // LDS.128 broadcast
            d0 = fma2(t.x, xp0[7 - 2 * m], d0);
            d1 = fma2(t.x, xp1[7 - 2 * m], d1);
            d2 = fma2(t.x, xp2[7 - 2 * m], d2);
            d3 = fma2(t.x, xp3[7 - 2 * m], d3);
            d0 = fma2(t.y, xp0[6 - 2 * m], d0);
            d1 = fma2(t.y, xp1[6 - 2 * m], d1);
            d2 = fma2(t.y, xp2[6 - 2 * m], d2);
            d3 = fma2(t.y, xp3[6 - 2 * m], d3);
        }
        ya0 = fma2(d0, dup2(yv.x), ya0);
        ya1 = fma2(d1, dup2(yv.y), ya1);
        ya2 = fma2(d2, dup2(yv.z), ya2);
        ya3 = fma2(d3, dup2(yv.w), ya3);
    }
}

// Recursive fully-unrolled pair chain for bucket B: all (w,v,M,off,p) constexpr.
template <int B, int J>
struct PairChain {
    static __device__ __forceinline__ void run(
        const ulonglong2* __restrict__ sS3u2, const ull* __restrict__ sS2,
        const float* __restrict__ sXs, const float4* __restrict__ sY4,
        int bg, int b0, int b1, int b2, int b3,
        const ull (&xp0)[8], const ull (&xp1)[8], const ull (&xp2)[8], const ull (&xp3)[8],
        ull& acc0, ull& acc1, ull& acc2, ull& acc3)
    {
        constexpr int rank = J * 8 + B;
        constexpr int w    = pr_w(rank);
        constexpr int v    = pr_v(rank);
        constexpr int M    = (rank_len(rank) + 1) / 2;
        constexpr int off2 = boff2(B, J);
        constexpr int p    = B * PPB + J;

        const float P0 = sXs[b0 * 17 + w] * sXs[b0 * 17 + v];
        const float P1 = sXs[b1 * 17 + w] * sXs[b1 * 17 + v];
        const float P2 = sXs[b2 * 17 + w] * sXs[b2 * 17 + v];
        const float P3 = sXs[b3 * 17 + w] * sXs[b3 * 17 + v];
        ull ya0 = 0ull, ya1 = 0ull, ya2 = 0ull, ya3 = 0ull;
        dot_block<M>(sS3u2 + off2, sS2 + p, sY4, bg, xp0, xp1, xp2, xp3,
                     ya0, ya1, ya2, ya3);
        acc0 = fma2(dup2(P0), ya0, acc0);
        acc1 = fma2(dup2(P1), ya1, acc1);
        acc2 = fma2(dup2(P2), ya2, acc2);
        acc3 = fma2(dup2(P3), ya3, acc3);

        PairChain<B, J + 1>::run(sS3u2, sS2, sXs, sY4, bg, b0, b1, b2, b3,
                                 xp0, xp1, xp2, xp3, acc0, acc1, acc2, acc3);
    }
};
template <int B>
struct PairChain<B, PPB> {
    static __device__ __forceinline__ void run(
        const ulonglong2*, const ull*, const float*, const float4*,
        int, int, int, int, int,
        const ull (&)[8], const ull (&)[8], const ull (&)[8], const ull (&)[8],
        ull&, ull&, ull&, ull&) {}
};

// Grid (c=256, btile=4). 512 threads: bg = tid&63 owns 4 b's; psplit = tid>>6
// owns one bucket (compile-time schedule). Lanes carry (even-i, odd-i).
__global__ __launch_bounds__(512, 1)
void sc_main(const float* __restrict__ x, const float* __restrict__ y,
             float* __restrict__ out) {
    extern __shared__ char smraw[];
    float* sS3 = reinterpret_cast<float*>(smraw);
    ull*   sS2 = reinterpret_cast<ull*>(sS3 + S3_PER_C);
    float* sXs = reinterpret_cast<float*>(sS2 + S2U_PER_C);
    float* sYf = sXs + 256 * 17;                 // float4 [e][bg][4]
    float* red = sYf + EDIM * 256;
    const ulonglong2* sS3u2 = reinterpret_cast<const ulonglong2*>(sS3);
    const float4* sY4 = reinterpret_cast<const float4*>(sYf);

    const int tid    = threadIdx.x;
    const int c      = blockIdx.x;
    const int base   = blockIdx.y * 256;
    const int bg     = tid & 63;
    const int psplit = tid >> 6;

    // ---- stage S3 / S2 (coalesced) ----
    {
        const float4* src = reinterpret_cast<const float4*>(S3g + c * S3_PER_C);
        float4* dst = reinterpret_cast<float4*>(sS3);
        for (int t = tid; t < S3_PER_C / 4; t += 512) dst[t] = src[t];
        for (int t = tid; t < S2U_PER_C; t += 512)
            sS2[t] = S2gu[c * S2U_PER_C + t];
    }
    // ---- stage x scalars ----
#pragma unroll
    for (int t = 0; t < 8; t++) {
        const int idx = tid + t * 512;            // 4096 = 256*16
        const int b = idx >> 4, i = idx & 15;
        sXs[b * 17 + i] = x[((base + b) * CDIM + c) * LDIM + i];
    }
    // ---- stage y float4 [e][bg][quad] ----
#pragma unroll
    for (int t = 0; t < 5; t++) {
        const int idx = tid + t * 512;            // 2560 = 10*256
        const int b = idx & 255, e = idx >> 8;
        sYf[e * 256 + (b & 63) * 4 + (b >> 6)] = y[(base + b) * EDIM + e];
    }
    __syncthreads();

    // ---- per-thread packed x (4 b's) ----
    const int b0 = bg, b1 = bg + 64, b2 = bg + 128, b3 = bg + 192;
    ull xp0[8], xp1[8], xp2[8], xp3[8];
#pragma unroll
    for (int q = 0; q < 8; q++) {
        xp0[q] = pk2(sXs[b0 * 17 + 2 * q], sXs[b0 * 17 + 2 * q + 1]);
        xp1[q] = pk2(sXs[b1 * 17 + 2 * q], sXs[b1 * 17 + 2 * q + 1]);
        xp2[q] = pk2(sXs[b2 * 17 + 2 * q], sXs[b2 * 17 + 2 * q + 1]);
        xp3[q] = pk2(sXs[b3 * 17 + 2 * q], sXs[b3 * 17 + 2 * q + 1]);
    }

    ull acc0 = 0ull, acc1 = 0ull, acc2 = 0ull, acc3 = 0ull;

    // one warp-uniform dispatch; each bucket fully unrolled at compile time
    switch (psplit) {
        case 0: PairChain<0, 0>::run(sS3u2, sS2, sXs, sY4, bg, b0, b1, b2, b3, xp0, xp1, xp2, xp3, acc0, acc1, acc2, acc3); break;
        case 1: PairChain<1, 0>::run(sS3u2, sS2, sXs, sY4, bg, b0, b1, b2, b3, xp0, xp1, xp2, xp3, acc0, acc1, acc2, acc3); break;
        case 2: PairChain<2, 0>::run(sS3u2, sS2, sXs, sY4, bg, b0, b1, b2, b3, xp0, xp1, xp2, xp3, acc0, acc1, acc2, acc3); break;
        case 3: PairChain<3, 0>::run(sS3u2, sS2, sXs, sY4, bg, b0, b1, b2, b3, xp0, xp1, xp2, xp3, acc0, acc1, acc2, acc3); break;
        case 4: PairChain<4, 0>::run(sS3u2, sS2, sXs, sY4, bg, b0, b1, b2, b3, xp0, xp1, xp2, xp3, acc0, acc1, acc2, acc3); break;
        case 5: PairChain<5, 0>::run(sS3u2, sS2, sXs, sY4, bg, b0, b1, b2, b3, xp0, xp1, xp2, xp3, acc0, acc1, acc2, acc3); break;
        case 6: PairChain<6, 0>::run(sS3u2, sS2, sXs, sY4, bg, b0, b1, b2, b3, xp0, xp1, xp2, xp3, acc0, acc1, acc2, acc3); break;
        default: PairChain<7, 0>::run(sS3u2, sS2, sXs, sY4, bg, b0, b1, b2, b3, xp0, xp1, xp2, xp3, acc0, acc1, acc2, acc3); break;
    }

    float lo, hi;
    float s0, s1, s2v, s3v;
    upk2(acc0, lo, hi); s0  = lo + hi;
    upk2(acc1, lo, hi); s1  = lo + hi;
    upk2(acc2, lo, hi); s2v = lo + hi;
    upk2(acc3, lo, hi); s3v = lo + hi;

    // ---- nu=1 (psplit 0 only) ----
    if (psplit == 0) {
        const float* v1 = V1g + c * V1_PER_C;
        float add0 = 0.f, add1 = 0.f, add2 = 0.f, add3 = 0.f;
#pragma unroll 1
        for (int e = 0; e < EDIM; e++) {
            float t0 = 0.f, t1 = 0.f, t2 = 0.f, t3 = 0.f;
#pragma unroll
            for (int w = 0; w < 16; w++) {
                const float vv = v1[e * 16 + w];
                t0 = fmaf(vv, sXs[b0 * 17 + w], t0);
                t1 = fmaf(vv, sXs[b1 * 17 + w], t1);
                t2 = fmaf(vv, sXs[b2 * 17 + w], t2);
                t3 = fmaf(vv, sXs[b3 * 17 + w], t3);
            }
            const float4 yv = sY4[e * 64 + bg];
            add0 = fmaf(yv.x, t0, add0);
            add1 = fmaf(yv.y, t1, add1);
            add2 = fmaf(yv.z, t2, add2);
            add3 = fmaf(yv.w, t3, add3);
        }
        s0 += add0; s1 += add1; s2v += add2; s3v += add3;
    }

    // ---- deterministic cross-split reduction ----
    red[psplit * 256 + b0] = s0;
    red[psplit * 256 + b1] = s1;
    red[psplit * 256 + b2] = s2v;
    red[psplit * 256 + b3] = s3v;
    __syncthreads();
    if (tid < 256) {
        float s = 0.f;
#pragma unroll
        for (int k = 0; k < 8; k++) s += red[k * 256 + tid];
        out[(base + tid) * CDIM + c] = s;
    }
}

// ---- launch --------------------------------------------------------------------
extern "C" void kernel_launch(void* const* d_in, const int* in_sizes, int n_in,
                              void* d_out, int out_size) {
    const float* x  = (const float*)d_in[0];
    const float* y  = (const float*)d_in[1];
    const float* U3 = (const float*)d_in[2];
    const float* U2 = (const float*)d_in[3];
    const float* U1 = (const float*)d_in[4];
    const float* W3 = (const float*)d_in[5];
    const float* W2 = (const float*)d_in[6];
    const float* W1 = (const float*)d_in[7];
    float* out = (float*)d_out;

    cudaFuncSetAttribute(k_s3, cudaFuncAttributeMaxDynamicSharedMemorySize, SMEM_KS3);
    cudaFuncSetAttribute(sc_main, cudaFuncAttributeMaxDynamicSharedMemorySize, SMEM_MAIN);

    k_tab<<<1, 256>>>();
    k_sym<<<(K3C * NSLOT_F + 255) / 256, 256>>>(U3);
    k_s3<<<CDIM, 512, SMEM_KS3>>>(W3, U2, W2, U1, W1);

    dim3 grid(CDIM, BDIM / 256);
    sc_main<<<grid, 512, SMEM_MAIN>>>(x, y, out);
}